// round 1
// baseline (speedup 1.0000x reference)
#include <cuda_runtime.h>
#include <cstdint>

#define NN 100000
#define EE 1600000
#define FIN 128
#define HID 64
#define NG 512
#define BN_EPS_F 1e-5f

// Scratch (allocation-free rule: __device__ globals).
// g_Y holds the "projected" per-node row used for gather; g_A the self+bias accumulator.
__device__ __align__(16) float g_Y[(size_t)NN * HID];
__device__ __align__(16) float g_A[(size_t)NN * HID];

__device__ __forceinline__ void red_add_v4(float* p, float a, float b, float c, float d) {
    asm volatile("red.global.add.v4.f32 [%0], {%1,%2,%3,%4};"
                 :: "l"(p), "f"(a), "f"(b), "f"(c), "f"(d) : "memory");
}

// ---------------------------------------------------------------- zero output
__global__ void k_zero(float* __restrict__ out, int n) {
    int i = blockIdx.x * blockDim.x + threadIdx.x;
    if (i < n) out[i] = 0.f;
}

// ------------------------------------------------- K1: Y = x @ W1a^T ; A = Y + b1a
// Outer-product matvec: thread = node, acc[64] in registers, W column broadcast from SMEM.
__global__ __launch_bounds__(256) void k_in_proj(
    const float* __restrict__ x, const float* __restrict__ W, const float* __restrict__ b)
{
    __shared__ float Wt[FIN][HID];   // Wt[k][f] = W[f][k]
    __shared__ float bs[HID];
    for (int i = threadIdx.x; i < FIN * HID; i += 256) {
        int k = i >> 6, f = i & 63;
        Wt[k][f] = W[f * FIN + k];
    }
    if (threadIdx.x < HID) bs[threadIdx.x] = b[threadIdx.x];
    __syncthreads();

    int node = blockIdx.x * 256 + threadIdx.x;
    if (node >= NN) return;

    const float4* xr = (const float4*)(x + (size_t)node * FIN);
    float acc[HID];
#pragma unroll
    for (int f = 0; f < HID; f++) acc[f] = 0.f;

    for (int k4 = 0; k4 < FIN / 4; k4++) {
        float4 xv = xr[k4];
#pragma unroll
        for (int s = 0; s < 4; s++) {
            float xs = (s == 0) ? xv.x : ((s == 1) ? xv.y : ((s == 2) ? xv.z : xv.w));
            const float4* wr = (const float4*)Wt[4 * k4 + s];
#pragma unroll
            for (int f4 = 0; f4 < 16; f4++) {
                float4 w = wr[f4];
                acc[4 * f4 + 0] = fmaf(xs, w.x, acc[4 * f4 + 0]);
                acc[4 * f4 + 1] = fmaf(xs, w.y, acc[4 * f4 + 1]);
                acc[4 * f4 + 2] = fmaf(xs, w.z, acc[4 * f4 + 2]);
                acc[4 * f4 + 3] = fmaf(xs, w.w, acc[4 * f4 + 3]);
            }
        }
    }

    float4* Yo = (float4*)(g_Y + (size_t)node * HID);
    float4* Ao = (float4*)(g_A + (size_t)node * HID);
#pragma unroll
    for (int f4 = 0; f4 < 16; f4++) {
        float4 v = make_float4(acc[4 * f4], acc[4 * f4 + 1], acc[4 * f4 + 2], acc[4 * f4 + 3]);
        Yo[f4] = v;
        Ao[f4] = make_float4(v.x + bs[4 * f4], v.y + bs[4 * f4 + 1],
                             v.z + bs[4 * f4 + 2], v.w + bs[4 * f4 + 3]);
    }
}

// ------------------------------------------------- scatter: A[dst] += Y[src]
// 16 threads per edge, one float4 each, vector RED (no return). Y/A are L2-resident.
__global__ __launch_bounds__(256) void k_scatter(const int* __restrict__ ei)
{
    long long t = (long long)blockIdx.x * 256 + threadIdx.x;
    int e = (int)(t >> 4);
    int part = (int)(t & 15);
    if (e >= EE) return;
    int s = ei[e];        // src row
    int d = ei[EE + e];   // dst row
    float4 v = ((const float4*)g_Y)[(size_t)s * 16 + part];
    red_add_v4(g_A + (size_t)d * HID + part * 4, v.x, v.y, v.z, v.w);
}

// ------------------------------------------------- K3a: H1 = relu(bn1(relu(A1) @ W1b^T + b1b))
// bn + b1b folded into scale/shift. Writes H1 into g_Y (Y1 is dead).
__global__ __launch_bounds__(256) void k_mlp_a(
    const float* __restrict__ W, const float* __restrict__ bb,
    const float* __restrict__ ga, const float* __restrict__ be,
    const float* __restrict__ mm, const float* __restrict__ vv)
{
    __shared__ float Wt[HID][HID];
    __shared__ float sc[HID], sh[HID];
    for (int i = threadIdx.x; i < HID * HID; i += 256) {
        int k = i >> 6, f = i & 63;
        Wt[k][f] = W[f * HID + k];
    }
    if (threadIdx.x < HID) {
        int f = threadIdx.x;
        float s = ga[f] * rsqrtf(vv[f] + BN_EPS_F);
        sc[f] = s;
        sh[f] = (bb[f] - mm[f]) * s + be[f];
    }
    __syncthreads();

    int node = blockIdx.x * 256 + threadIdx.x;
    if (node >= NN) return;

    const float4* ar = (const float4*)(g_A + (size_t)node * HID);
    float acc[HID];
#pragma unroll
    for (int f = 0; f < HID; f++) acc[f] = 0.f;

    for (int k4 = 0; k4 < HID / 4; k4++) {
        float4 av = ar[k4];
        av.x = fmaxf(av.x, 0.f); av.y = fmaxf(av.y, 0.f);
        av.z = fmaxf(av.z, 0.f); av.w = fmaxf(av.w, 0.f);
#pragma unroll
        for (int s = 0; s < 4; s++) {
            float xs = (s == 0) ? av.x : ((s == 1) ? av.y : ((s == 2) ? av.z : av.w));
            const float4* wr = (const float4*)Wt[4 * k4 + s];
#pragma unroll
            for (int f4 = 0; f4 < 16; f4++) {
                float4 w = wr[f4];
                acc[4 * f4 + 0] = fmaf(xs, w.x, acc[4 * f4 + 0]);
                acc[4 * f4 + 1] = fmaf(xs, w.y, acc[4 * f4 + 1]);
                acc[4 * f4 + 2] = fmaf(xs, w.z, acc[4 * f4 + 2]);
                acc[4 * f4 + 3] = fmaf(xs, w.w, acc[4 * f4 + 3]);
            }
        }
    }

    float4* Ho = (float4*)(g_Y + (size_t)node * HID);
#pragma unroll
    for (int f4 = 0; f4 < 16; f4++) {
        float4 h;
        h.x = fmaxf(fmaf(acc[4 * f4 + 0], sc[4 * f4 + 0], sh[4 * f4 + 0]), 0.f);
        h.y = fmaxf(fmaf(acc[4 * f4 + 1], sc[4 * f4 + 1], sh[4 * f4 + 1]), 0.f);
        h.z = fmaxf(fmaf(acc[4 * f4 + 2], sc[4 * f4 + 2], sh[4 * f4 + 2]), 0.f);
        h.w = fmaxf(fmaf(acc[4 * f4 + 3], sc[4 * f4 + 3], sh[4 * f4 + 3]), 0.f);
        Ho[f4] = h;
    }
}

// ------------------------------------------------- K3b: Y2 = H1 @ W2a^T (in place in g_Y); A2 = Y2 + b2a
__global__ __launch_bounds__(256) void k_proj_h(
    const float* __restrict__ W, const float* __restrict__ b)
{
    __shared__ float Wt[HID][HID];
    __shared__ float bs[HID];
    for (int i = threadIdx.x; i < HID * HID; i += 256) {
        int k = i >> 6, f = i & 63;
        Wt[k][f] = W[f * HID + k];
    }
    if (threadIdx.x < HID) bs[threadIdx.x] = b[threadIdx.x];
    __syncthreads();

    int node = blockIdx.x * 256 + threadIdx.x;
    if (node >= NN) return;

    const float4* hr = (const float4*)(g_Y + (size_t)node * HID);
    float acc[HID];
#pragma unroll
    for (int f = 0; f < HID; f++) acc[f] = 0.f;

    for (int k4 = 0; k4 < HID / 4; k4++) {
        float4 hv = hr[k4];
#pragma unroll
        for (int s = 0; s < 4; s++) {
            float xs = (s == 0) ? hv.x : ((s == 1) ? hv.y : ((s == 2) ? hv.z : hv.w));
            const float4* wr = (const float4*)Wt[4 * k4 + s];
#pragma unroll
            for (int f4 = 0; f4 < 16; f4++) {
                float4 w = wr[f4];
                acc[4 * f4 + 0] = fmaf(xs, w.x, acc[4 * f4 + 0]);
                acc[4 * f4 + 1] = fmaf(xs, w.y, acc[4 * f4 + 1]);
                acc[4 * f4 + 2] = fmaf(xs, w.z, acc[4 * f4 + 2]);
                acc[4 * f4 + 3] = fmaf(xs, w.w, acc[4 * f4 + 3]);
            }
        }
    }

    float4* Yo = (float4*)(g_Y + (size_t)node * HID);
    float4* Ao = (float4*)(g_A + (size_t)node * HID);
#pragma unroll
    for (int f4 = 0; f4 < 16; f4++) {
        float4 v = make_float4(acc[4 * f4], acc[4 * f4 + 1], acc[4 * f4 + 2], acc[4 * f4 + 3]);
        Yo[f4] = v;
        Ao[f4] = make_float4(v.x + bs[4 * f4], v.y + bs[4 * f4 + 1],
                             v.z + bs[4 * f4 + 2], v.w + bs[4 * f4 + 3]);
    }
}

// ------------------------------------------------- K5: final MLP + bn2 + relu + mean-pool (sum part)
__global__ __launch_bounds__(256) void k_final(
    const float* __restrict__ W, const float* __restrict__ bb,
    const float* __restrict__ ga, const float* __restrict__ be,
    const float* __restrict__ mm, const float* __restrict__ vv,
    const int* __restrict__ batch, float* __restrict__ out)
{
    __shared__ float Wt[HID][HID];
    __shared__ float sc[HID], sh[HID];
    for (int i = threadIdx.x; i < HID * HID; i += 256) {
        int k = i >> 6, f = i & 63;
        Wt[k][f] = W[f * HID + k];
    }
    if (threadIdx.x < HID) {
        int f = threadIdx.x;
        float s = ga[f] * rsqrtf(vv[f] + BN_EPS_F);
        sc[f] = s;
        sh[f] = (bb[f] - mm[f]) * s + be[f];
    }
    __syncthreads();

    int node = blockIdx.x * 256 + threadIdx.x;
    if (node >= NN) return;   // N % 32 == 0: whole warps exit together

    const float4* ar = (const float4*)(g_A + (size_t)node * HID);
    float acc[HID];
#pragma unroll
    for (int f = 0; f < HID; f++) acc[f] = 0.f;

    for (int k4 = 0; k4 < HID / 4; k4++) {
        float4 av = ar[k4];
        av.x = fmaxf(av.x, 0.f); av.y = fmaxf(av.y, 0.f);
        av.z = fmaxf(av.z, 0.f); av.w = fmaxf(av.w, 0.f);
#pragma unroll
        for (int s = 0; s < 4; s++) {
            float xs = (s == 0) ? av.x : ((s == 1) ? av.y : ((s == 2) ? av.z : av.w));
            const float4* wr = (const float4*)Wt[4 * k4 + s];
#pragma unroll
            for (int f4 = 0; f4 < 16; f4++) {
                float4 w = wr[f4];
                acc[4 * f4 + 0] = fmaf(xs, w.x, acc[4 * f4 + 0]);
                acc[4 * f4 + 1] = fmaf(xs, w.y, acc[4 * f4 + 1]);
                acc[4 * f4 + 2] = fmaf(xs, w.z, acc[4 * f4 + 2]);
                acc[4 * f4 + 3] = fmaf(xs, w.w, acc[4 * f4 + 3]);
            }
        }
    }

    // bn2 + relu (b2b folded into sh)
#pragma unroll
    for (int j = 0; j < HID; j++)
        acc[j] = fmaxf(fmaf(acc[j], sc[j], sh[j]), 0.f);

    int g = batch[node];
    int lane = threadIdx.x & 31;
    int g0 = __shfl_sync(0xffffffffu, g, 0);
    bool uni = __all_sync(0xffffffffu, g == g0);

    if (uni) {
        // batch is sorted: most warps are graph-uniform. Butterfly-reduce across lanes,
        // then 16 single-lane vector REDs instead of 512 contended scalar atomics.
#pragma unroll
        for (int j = 0; j < HID; j++) {
            float v = acc[j];
            v += __shfl_xor_sync(0xffffffffu, v, 1);
            v += __shfl_xor_sync(0xffffffffu, v, 2);
            v += __shfl_xor_sync(0xffffffffu, v, 4);
            v += __shfl_xor_sync(0xffffffffu, v, 8);
            v += __shfl_xor_sync(0xffffffffu, v, 16);
            acc[j] = v;
        }
        float* base = out + (size_t)g * HID;
#pragma unroll
        for (int j4 = 0; j4 < 16; j4++) {
            if (lane == j4)
                red_add_v4(base + 4 * j4, acc[4 * j4], acc[4 * j4 + 1],
                           acc[4 * j4 + 2], acc[4 * j4 + 3]);
        }
    } else {
        // rare boundary warp: per-lane vector REDs
        float* base = out + (size_t)g * HID;
#pragma unroll
        for (int j4 = 0; j4 < 16; j4++)
            red_add_v4(base + 4 * j4, acc[4 * j4], acc[4 * j4 + 1],
                       acc[4 * j4 + 2], acc[4 * j4 + 3]);
    }
}

// ------------------------------------------------- K6: divide by per-graph counts (batch sorted -> binary search)
__global__ void k_div(const int* __restrict__ batch, float* __restrict__ out)
{
    int g = blockIdx.x;
    __shared__ int cnt;
    if (threadIdx.x == 0) {
        int lo = 0, hi = NN;
        while (lo < hi) { int mid = (lo + hi) >> 1; if (batch[mid] < g) lo = mid + 1; else hi = mid; }
        int lo2 = lo, hi2 = NN;
        while (lo2 < hi2) { int mid = (lo2 + hi2) >> 1; if (batch[mid] < g + 1) lo2 = mid + 1; else hi2 = mid; }
        cnt = lo2 - lo;
    }
    __syncthreads();
    float c = (float)(cnt > 1 ? cnt : 1);
    out[(size_t)g * HID + threadIdx.x] /= c;
}

// ---------------------------------------------------------------- launch
extern "C" void kernel_launch(void* const* d_in, const int* in_sizes, int n_in,
                              void* d_out, int out_size)
{
    (void)in_sizes; (void)n_in; (void)out_size;
    const float* x    = (const float*)d_in[0];
    const int*   ei   = (const int*)d_in[1];     // edge_index [2, E] int32
    const int*   batch= (const int*)d_in[2];
    const float* W1a  = (const float*)d_in[3];
    const float* b1a  = (const float*)d_in[4];
    const float* W1b  = (const float*)d_in[5];
    const float* b1b  = (const float*)d_in[6];
    const float* g1   = (const float*)d_in[7];
    const float* be1  = (const float*)d_in[8];
    const float* m1   = (const float*)d_in[9];
    const float* v1   = (const float*)d_in[10];
    const float* W2a  = (const float*)d_in[11];
    const float* b2a  = (const float*)d_in[12];
    const float* W2b  = (const float*)d_in[13];
    const float* b2b  = (const float*)d_in[14];
    const float* g2   = (const float*)d_in[15];
    const float* be2  = (const float*)d_in[16];
    const float* m2   = (const float*)d_in[17];
    const float* v2   = (const float*)d_in[18];
    float* out = (float*)d_out;

    int nodeBlocks = (NN + 255) / 256;
    int edgeBlocks = (EE * 16) / 256;   // 100000, exact

    k_zero<<<(NG * HID + 255) / 256, 256>>>(out, NG * HID);
    k_in_proj<<<nodeBlocks, 256>>>(x, W1a, b1a);
    k_scatter<<<edgeBlocks, 256>>>(ei);
    k_mlp_a<<<nodeBlocks, 256>>>(W1b, b1b, g1, be1, m1, v1);
    k_proj_h<<<nodeBlocks, 256>>>(W2a, b2a);
    k_scatter<<<edgeBlocks, 256>>>(ei);
    k_final<<<nodeBlocks, 256>>>(W2b, b2b, g2, be2, m2, v2, batch, out);
    k_div<<<NG, HID>>>(batch, out);
}